// round 4
// baseline (speedup 1.0000x reference)
#include <cuda_runtime.h>
#include <math.h>

// Problem constants
#define B_    8
#define N_    4096
#define C_    1024
#define NB    256      // coarse blocks of 16 samples per batch
#define CHUNK 8        // coarse blocks per thread in reconstruction

// --------------------------------------------------------------------------
// Scratch (static __device__ — no allocation anywhere)
// --------------------------------------------------------------------------
__device__ float d_e0[B_ * 2048];   // scale-0 detail energy (len 2048 per b)
__device__ float d_e1[B_ * 1024];   // scale-1
__device__ float d_e2[B_ * 512];    // scale-2
__device__ float d_g0[B_ * 2048];   // gates = (e > thr) ? sigmoid(sw_i) : 0
__device__ float d_g1[B_ * 1024];
__device__ float d_g2[B_ * 512];
__device__ float d_thr[3];
__device__ float d_Gmix;            // (mean cw1 + .5 mean cw2 + .2 mean cw3) * sigmoid(rw)

__device__ __forceinline__ float sigm(float v) { return 1.0f / (1.0f + expf(-v)); }

// --------------------------------------------------------------------------
// Pass 1: detail energies for scales 0,1,2 (scale-3 detail is unused by the
// reference reconstruction — only its approx is used).
// Block = (coarse block t, batch b). 256 threads x 4 c-iterations over C=1024.
// --------------------------------------------------------------------------
__global__ __launch_bounds__(256) void energy_kernel(const float* __restrict__ x) {
    int t = blockIdx.x;
    int b = blockIdx.y;
    const float* xp = x + ((size_t)b * N_ + (size_t)t * 16) * C_;

    float acc[14];
#pragma unroll
    for (int i = 0; i < 14; i++) acc[i] = 0.f;

    for (int it = 0; it < 4; ++it) {
        int c = threadIdx.x + it * 256;
        float v[16];
#pragma unroll
        for (int k = 0; k < 16; k++) v[k] = xp[(size_t)k * C_ + c];
        float a1[8];
#pragma unroll
        for (int j = 0; j < 8; j++) {
            float d = (v[2 * j] - v[2 * j + 1]) * 0.5f;
            acc[j] += d * d;
            a1[j] = (v[2 * j] + v[2 * j + 1]) * 0.5f;
        }
        float a2[4];
#pragma unroll
        for (int j = 0; j < 4; j++) {
            float d = (a1[2 * j] - a1[2 * j + 1]) * 0.5f;
            acc[8 + j] += d * d;
            a2[j] = (a1[2 * j] + a1[2 * j + 1]) * 0.5f;
        }
#pragma unroll
        for (int j = 0; j < 2; j++) {
            float d = (a2[2 * j] - a2[2 * j + 1]) * 0.5f;
            acc[12 + j] += d * d;
        }
    }

    __shared__ float red[8][14];
    int lane = threadIdx.x & 31, wid = threadIdx.x >> 5;
#pragma unroll
    for (int i = 0; i < 14; i++) {
        float v = acc[i];
#pragma unroll
        for (int o = 16; o > 0; o >>= 1) v += __shfl_down_sync(0xffffffffu, v, o);
        if (lane == 0) red[wid][i] = v;
    }
    __syncthreads();
    int tid = threadIdx.x;
    if (tid < 14) {
        float s = 0.f;
#pragma unroll
        for (int w = 0; w < 8; w++) s += red[w][tid];
        s *= (1.0f / 1024.0f);   // mean over C
        if (tid < 8)       d_e0[b * 2048 + t * 8 + tid] = s;
        else if (tid < 12) d_e1[b * 1024 + t * 4 + (tid - 8)] = s;
        else               d_e2[b * 512 + t * 2 + (tid - 12)] = s;
    }
}

// --------------------------------------------------------------------------
// Pass 2: per-scale quantile thresholds via radix-select (energies >= 0, so
// float bit pattern order == value order). Block 3 computes scalar G.
// blockDim must be 1024.
// --------------------------------------------------------------------------
__device__ int block_reduce_sum_i(int v) {
    __shared__ int sw_[32];
    __shared__ int stot;
    int lane = threadIdx.x & 31, wid = threadIdx.x >> 5;
#pragma unroll
    for (int o = 16; o > 0; o >>= 1) v += __shfl_down_sync(0xffffffffu, v, o);
    if (lane == 0) sw_[wid] = v;
    __syncthreads();
    if (wid == 0) {
        int xv = sw_[lane];
#pragma unroll
        for (int o = 16; o > 0; o >>= 1) xv += __shfl_down_sync(0xffffffffu, xv, o);
        if (lane == 0) stot = xv;
    }
    __syncthreads();
    return stot;
}

__device__ float block_reduce_sum_f(float v) {
    __shared__ float swf[32];
    __shared__ float ftot;
    int lane = threadIdx.x & 31, wid = threadIdx.x >> 5;
#pragma unroll
    for (int o = 16; o > 0; o >>= 1) v += __shfl_down_sync(0xffffffffu, v, o);
    if (lane == 0) swf[wid] = v;
    __syncthreads();
    if (wid == 0) {
        float xv = swf[lane];
#pragma unroll
        for (int o = 16; o > 0; o >>= 1) xv += __shfl_down_sync(0xffffffffu, xv, o);
        if (lane == 0) ftot = xv;
    }
    __syncthreads();
    return ftot;
}

// k-th smallest (0-indexed) over the block's cached register copy of the array.
__device__ float block_select_kth(const unsigned (&eb)[16], int m, int k) {
    unsigned prefix = 0, dmask = 0;
    for (int bit = 31; bit >= 0; --bit) {
        unsigned bb = 1u << bit;
        int cnt = 0;
#pragma unroll
        for (int i = 0; i < 16; i++)
            if (i < m && (eb[i] & (dmask | bb)) == prefix) cnt++;
        int tot = block_reduce_sum_i(cnt);
        if (k >= tot) { k -= tot; prefix |= bb; }
        dmask |= bb;
    }
    return __uint_as_float(prefix);
}

__global__ __launch_bounds__(1024) void thresh_kernel(
    const float* __restrict__ qp,
    const float* __restrict__ cw1, const float* __restrict__ cw2,
    const float* __restrict__ cw3, const float* __restrict__ rw) {
    int bid = blockIdx.x, tid = threadIdx.x;

    if (bid == 3) {   // scalar mixing weight G
        float s1 = block_reduce_sum_f(cw1[tid]);
        float s2 = block_reduce_sum_f(cw2[tid]);
        float s3 = block_reduce_sum_f(cw3[tid]);
        if (tid == 0) {
            float m1 = s1 * (1.f / 1024.f), m2 = s2 * (1.f / 1024.f), m3 = s3 * (1.f / 1024.f);
            d_Gmix = (m1 + 0.5f * m2 + 0.2f * m3) * sigm(rw[0]);
        }
        return;
    }

    const float* e = (bid == 0) ? d_e0 : (bid == 1) ? d_e1 : d_e2;
    int n = (bid == 0) ? B_ * 2048 : (bid == 1) ? B_ * 1024 : B_ * 512;
    int m = n >> 10;  // elements per thread (16/8/4)

    unsigned eb[16];
#pragma unroll
    for (int i = 0; i < 16; i++)
        eb[i] = (i < m) ? __float_as_uint(e[tid + (i << 10)]) : 0xffffffffu;

    // torch.quantile 'linear': idx = q*(n-1); interp between s[lo], s[lo+1]
    float qv = qp[0];
    float idxf = qv * (float)(n - 1);
    int lo = (int)floorf(idxf);
    if (lo < 0) lo = 0;
    if (lo > n - 1) lo = n - 1;
    int hi = lo + 1;
    if (hi > n - 1) hi = n - 1;
    float frac = idxf - (float)lo;

    float vlo = block_select_kth(eb, m, lo);
    float vhi = (hi == lo) ? vlo : block_select_kth(eb, m, hi);
    if (tid == 0) d_thr[bid] = vlo * (1.0f - frac) + vhi * frac;
}

// --------------------------------------------------------------------------
// Pass 2b: gates g_i[b,l] = (e > thr_i) ? sigmoid(scale_weights[i]) : 0
// --------------------------------------------------------------------------
__global__ void gates_kernel(const float* __restrict__ sweights) {
    int i = blockIdx.x * blockDim.x + threadIdx.x;
    if (i < B_ * 2048) {
        d_g0[i] = (d_e0[i] > d_thr[0]) ? sigm(sweights[0]) : 0.0f;
    } else if (i < B_ * 2048 + B_ * 1024) {
        int j = i - B_ * 2048;
        d_g1[j] = (d_e1[j] > d_thr[1]) ? sigm(sweights[1]) : 0.0f;
    } else if (i < B_ * 2048 + B_ * 1024 + B_ * 512) {
        int j = i - B_ * 2048 - B_ * 1024;
        d_g2[j] = (d_e2[j] > d_thr[2]) ? sigm(sweights[2]) : 0.0f;
    }
}

// --------------------------------------------------------------------------
// Pass 3: fused decompose + threshold + multi-level linear-upsample synthesis.
// Streaming recurrence per channel with 1-coarse-block lookahead.
//   up[2m]   = 0.25 R[m-1] + 0.75 R[m]      (index-clamped == reference clip)
//   up[2m+1] = 0.75 R[m]   + 0.25 R[m+1]
// --------------------------------------------------------------------------
__device__ __forceinline__ void decomp_block(const float* __restrict__ p,
                                             float (&D0)[8], float (&D1)[4],
                                             float (&D2)[2], float& A3) {
    float v[16];
#pragma unroll
    for (int k = 0; k < 16; k++) v[k] = p[(size_t)k * C_];
    float a1[8];
#pragma unroll
    for (int j = 0; j < 8; j++) {
        D0[j] = (v[2 * j] - v[2 * j + 1]) * 0.5f;
        a1[j] = (v[2 * j] + v[2 * j + 1]) * 0.5f;
    }
    float a2[4];
#pragma unroll
    for (int j = 0; j < 4; j++) {
        D1[j] = (a1[2 * j] - a1[2 * j + 1]) * 0.5f;
        a2[j] = (a1[2 * j] + a1[2 * j + 1]) * 0.5f;
    }
    float a3[2];
#pragma unroll
    for (int j = 0; j < 2; j++) {
        D2[j] = (a2[2 * j] - a2[2 * j + 1]) * 0.5f;
        a3[j] = (a2[2 * j] + a2[2 * j + 1]) * 0.5f;
    }
    A3 = (a3[0] + a3[1]) * 0.5f;
}

__global__ __launch_bounds__(256) void recon_kernel(const float* __restrict__ x,
                                                    float* __restrict__ out,
                                                    const float* __restrict__ sweights) {
    int c  = blockIdx.x * 256 + threadIdx.x;
    int t0 = blockIdx.y * CHUNK;
    int b  = blockIdx.z;

    float sw3 = sigm(sweights[3]);
    float G   = d_Gmix;
    const float* xb = x   + (size_t)b * N_ * C_ + c;
    float*       ob = out + (size_t)b * N_ * C_ + c;
    const float* g0 = d_g0 + b * 2048;
    const float* g1 = d_g1 + b * 1024;
    const float* g2 = d_g2 + b * 512;

    float D0c[8], D1c[4], D2c[2], A3c;
    decomp_block(xb + (size_t)t0 * 16 * C_, D0c, D1c, D2c, A3c);

    float pR256, pR512, pR1024, pR2048;
    if (t0 == 0) {
        // left-edge clamp: prev values equal the first values
        float R = sw3 * A3c;
        pR256  = R;
        pR512  = R + g2[0] * D2c[0];
        pR1024 = pR512 + g1[0] * D1c[0];
        pR2048 = pR1024 + g0[0] * D0c[0];
    } else {
        // warm-up from halo block t0-1
        float D0p[8], D1p[4], D2p[2], A3p;
        decomp_block(xb + (size_t)(t0 - 1) * 16 * C_, D0p, D1p, D2p, A3p);
        float Rm = sw3 * A3p, Rc = sw3 * A3c;
        float R512m  = 0.75f * Rm + 0.25f * Rc + g2[2 * t0 - 1] * D2p[1];
        float R512_0 = 0.25f * Rm + 0.75f * Rc + g2[2 * t0]     * D2c[0];
        float R1024m  = 0.75f * R512m + 0.25f * R512_0 + g1[4 * t0 - 1] * D1p[3];
        float R1024_0 = 0.25f * R512m + 0.75f * R512_0 + g1[4 * t0]     * D1c[0];
        pR2048 = 0.75f * R1024m + 0.25f * R1024_0 + g0[8 * t0 - 1] * D0p[7];
        pR256 = Rm; pR512 = R512m; pR1024 = R1024m;
    }

#pragma unroll 1
    for (int tt = 0; tt < CHUNK; ++tt) {
        int t = t0 + tt;
        bool lastb = (t == NB - 1);
        int tn = lastb ? t : t + 1;

        float D0n[8], D1n[4], D2n[2], A3n;
        decomp_block(xb + (size_t)tn * 16 * C_, D0n, D1n, D2n, A3n);

        float cR256 = sw3 * A3c;
        float nR256 = lastb ? cR256 : sw3 * A3n;

        float r512_0 = 0.25f * pR256 + 0.75f * cR256 + g2[2 * t]     * D2c[0];
        float r512_1 = 0.75f * cR256 + 0.25f * nR256 + g2[2 * t + 1] * D2c[1];
        int i2 = 2 * t + 2; if (i2 > 511) i2 = 511;
        float nR512 = lastb ? r512_1
                            : (0.25f * cR256 + 0.75f * nR256 + g2[i2] * D2n[0]);

        float r1024_0 = 0.25f * pR512  + 0.75f * r512_0 + g1[4 * t]     * D1c[0];
        float r1024_1 = 0.75f * r512_0 + 0.25f * r512_1 + g1[4 * t + 1] * D1c[1];
        float r1024_2 = 0.25f * r512_0 + 0.75f * r512_1 + g1[4 * t + 2] * D1c[2];
        float r1024_3 = 0.75f * r512_1 + 0.25f * nR512  + g1[4 * t + 3] * D1c[3];
        int i1 = 4 * t + 4; if (i1 > 1023) i1 = 1023;
        float nR1024 = lastb ? r1024_3
                             : (0.25f * r512_1 + 0.75f * nR512 + g1[i1] * D1n[0]);

        float r2048[8];
        r2048[0] = 0.25f * pR1024  + 0.75f * r1024_0 + g0[8 * t + 0] * D0c[0];
        r2048[1] = 0.75f * r1024_0 + 0.25f * r1024_1 + g0[8 * t + 1] * D0c[1];
        r2048[2] = 0.25f * r1024_0 + 0.75f * r1024_1 + g0[8 * t + 2] * D0c[2];
        r2048[3] = 0.75f * r1024_1 + 0.25f * r1024_2 + g0[8 * t + 3] * D0c[3];
        r2048[4] = 0.25f * r1024_1 + 0.75f * r1024_2 + g0[8 * t + 4] * D0c[4];
        r2048[5] = 0.75f * r1024_2 + 0.25f * r1024_3 + g0[8 * t + 5] * D0c[5];
        r2048[6] = 0.25f * r1024_2 + 0.75f * r1024_3 + g0[8 * t + 6] * D0c[6];
        r2048[7] = 0.75f * r1024_3 + 0.25f * nR1024  + g0[8 * t + 7] * D0c[7];
        int i0 = 8 * t + 8; if (i0 > 2047) i0 = 2047;
        float nR2048 = lastb ? r2048[7]
                             : (0.25f * r1024_3 + 0.75f * nR1024 + g0[i0] * D0n[0]);

        float* op = ob + (size_t)t * 16 * C_;
        op[0 * C_]  = (0.25f * pR2048   + 0.75f * r2048[0]) * G;
        op[1 * C_]  = (0.75f * r2048[0] + 0.25f * r2048[1]) * G;
        op[2 * C_]  = (0.25f * r2048[0] + 0.75f * r2048[1]) * G;
        op[3 * C_]  = (0.75f * r2048[1] + 0.25f * r2048[2]) * G;
        op[4 * C_]  = (0.25f * r2048[1] + 0.75f * r2048[2]) * G;
        op[5 * C_]  = (0.75f * r2048[2] + 0.25f * r2048[3]) * G;
        op[6 * C_]  = (0.25f * r2048[2] + 0.75f * r2048[3]) * G;
        op[7 * C_]  = (0.75f * r2048[3] + 0.25f * r2048[4]) * G;
        op[8 * C_]  = (0.25f * r2048[3] + 0.75f * r2048[4]) * G;
        op[9 * C_]  = (0.75f * r2048[4] + 0.25f * r2048[5]) * G;
        op[10 * C_] = (0.25f * r2048[4] + 0.75f * r2048[5]) * G;
        op[11 * C_] = (0.75f * r2048[5] + 0.25f * r2048[6]) * G;
        op[12 * C_] = (0.25f * r2048[5] + 0.75f * r2048[6]) * G;
        op[13 * C_] = (0.75f * r2048[6] + 0.25f * r2048[7]) * G;
        op[14 * C_] = (0.25f * r2048[6] + 0.75f * r2048[7]) * G;
        op[15 * C_] = (0.75f * r2048[7] + 0.25f * nR2048)   * G;

        pR256 = cR256; pR512 = r512_1; pR1024 = r1024_3; pR2048 = r2048[7];
#pragma unroll
        for (int j = 0; j < 8; j++) D0c[j] = D0n[j];
#pragma unroll
        for (int j = 0; j < 4; j++) D1c[j] = D1n[j];
        D2c[0] = D2n[0]; D2c[1] = D2n[1];
        A3c = A3n;
    }
}

// --------------------------------------------------------------------------
// Launch
// --------------------------------------------------------------------------
extern "C" void kernel_launch(void* const* d_in, const int* in_sizes, int n_in,
                              void* d_out, int out_size) {
    const float* x   = (const float*)d_in[0];
    const float* cw1 = (const float*)d_in[1];
    const float* cw2 = (const float*)d_in[2];
    const float* cw3 = (const float*)d_in[3];
    const float* qp  = (const float*)d_in[4];
    const float* sw  = (const float*)d_in[5];
    const float* rw  = (const float*)d_in[6];
    float* out = (float*)d_out;

    energy_kernel<<<dim3(NB, B_), 256>>>(x);
    thresh_kernel<<<4, 1024>>>(qp, cw1, cw2, cw3, rw);
    int ng = B_ * 2048 + B_ * 1024 + B_ * 512;
    gates_kernel<<<(ng + 255) / 256, 256>>>(sw);
    recon_kernel<<<dim3(C_ / 256, NB / CHUNK, B_), 256>>>(x, out, sw);
}

// round 5
// speedup vs baseline: 1.4388x; 1.4388x over previous
#include <cuda_runtime.h>
#include <math.h>

// Problem constants
#define B_    8
#define N_    4096
#define C_    1024
#define NB    256      // coarse blocks of 16 samples per batch
#define CHUNK 4        // coarse blocks per thread-chunk in reconstruction

// --------------------------------------------------------------------------
// Scratch (static __device__ — no allocation anywhere)
// --------------------------------------------------------------------------
__device__ float d_e0[B_ * 2048];   // scale-0 detail energy
__device__ float d_e1[B_ * 1024];   // scale-1
__device__ float d_e2[B_ * 512];    // scale-2
__device__ float d_g0[B_ * 2048];   // gates = (e > thr) ? sigmoid(sw_i) : 0
__device__ float d_g1[B_ * 1024];
__device__ float d_g2[B_ * 512];
__device__ float d_Gmix;            // (mean cw1 + .5 mean cw2 + .2 mean cw3) * sigmoid(rw)

__device__ __forceinline__ float sigm(float v) { return 1.0f / (1.0f + expf(-v)); }

// --------------------------------------------------------------------------
// Pass 1: detail energies for scales 0,1,2 (scale-3 detail unused by the
// reference reconstruction). Block = (coarse block t, batch b).
// --------------------------------------------------------------------------
__global__ __launch_bounds__(256) void energy_kernel(const float* __restrict__ x) {
    int t = blockIdx.x;
    int b = blockIdx.y;
    const float* xp = x + ((size_t)b * N_ + (size_t)t * 16) * C_;

    float acc[14];
#pragma unroll
    for (int i = 0; i < 14; i++) acc[i] = 0.f;

    for (int it = 0; it < 4; ++it) {
        int c = threadIdx.x + it * 256;
        float v[16];
#pragma unroll
        for (int k = 0; k < 16; k++) v[k] = xp[(size_t)k * C_ + c];
        float a1[8];
#pragma unroll
        for (int j = 0; j < 8; j++) {
            float d = (v[2 * j] - v[2 * j + 1]) * 0.5f;
            acc[j] += d * d;
            a1[j] = (v[2 * j] + v[2 * j + 1]) * 0.5f;
        }
        float a2[4];
#pragma unroll
        for (int j = 0; j < 4; j++) {
            float d = (a1[2 * j] - a1[2 * j + 1]) * 0.5f;
            acc[8 + j] += d * d;
            a2[j] = (a1[2 * j] + a1[2 * j + 1]) * 0.5f;
        }
#pragma unroll
        for (int j = 0; j < 2; j++) {
            float d = (a2[2 * j] - a2[2 * j + 1]) * 0.5f;
            acc[12 + j] += d * d;
        }
    }

    __shared__ float red[8][14];
    int lane = threadIdx.x & 31, wid = threadIdx.x >> 5;
#pragma unroll
    for (int i = 0; i < 14; i++) {
        float v = acc[i];
#pragma unroll
        for (int o = 16; o > 0; o >>= 1) v += __shfl_down_sync(0xffffffffu, v, o);
        if (lane == 0) red[wid][i] = v;
    }
    __syncthreads();
    int tid = threadIdx.x;
    if (tid < 14) {
        float s = 0.f;
#pragma unroll
        for (int w = 0; w < 8; w++) s += red[w][tid];
        s *= (1.0f / 1024.0f);   // mean over C
        if (tid < 8)       d_e0[b * 2048 + t * 8 + tid] = s;
        else if (tid < 12) d_e1[b * 1024 + t * 4 + (tid - 8)] = s;
        else               d_e2[b * 512 + t * 2 + (tid - 12)] = s;
    }
}

// --------------------------------------------------------------------------
// Pass 2: quantile thresholds via radix-256 select (4 rounds per rank),
// fused gate writes. Energies >= 0 so float-bit order == value order.
// blockDim must be 1024. Block 3 computes scalar G.
// --------------------------------------------------------------------------
__device__ float block_reduce_sum_f(float v) {
    __shared__ float swf[32];
    __shared__ float ftot;
    int lane = threadIdx.x & 31, wid = threadIdx.x >> 5;
#pragma unroll
    for (int o = 16; o > 0; o >>= 1) v += __shfl_down_sync(0xffffffffu, v, o);
    if (lane == 0) swf[wid] = v;
    __syncthreads();
    if (wid == 0) {
        float xv = swf[lane];
#pragma unroll
        for (int o = 16; o > 0; o >>= 1) xv += __shfl_down_sync(0xffffffffu, xv, o);
        if (lane == 0) ftot = xv;
    }
    __syncthreads();
    return ftot;
}

// k-th smallest (0-indexed) over the block's register-cached array.
// 4 rounds of radix-256 (byte from high to low).
__device__ float radix_select_kth(const unsigned (&eb)[16], int m, int k) {
    __shared__ int hist[256];
    __shared__ int swtot[8], swoff[8];
    __shared__ unsigned s_prefix;
    __shared__ int s_k;
    int tid = threadIdx.x;
    unsigned prefix = 0;

    for (int r = 3; r >= 0; --r) {
        if (tid < 256) hist[tid] = 0;
        __syncthreads();

        int shift = r * 8;
        unsigned pmask = (r == 3) ? 0u : (0xFFFFFFFFu << (shift + 8));
#pragma unroll
        for (int i = 0; i < 16; i++) {
            if (i < m && (eb[i] & pmask) == prefix)
                atomicAdd(&hist[(eb[i] >> shift) & 0xFFu], 1);
        }
        __syncthreads();

        // 256-bin inclusive scan: warp shfl scan + 8 warp totals
        int c = (tid < 256) ? hist[tid] : 0;
        int incl = c;
#pragma unroll
        for (int off = 1; off < 32; off <<= 1) {
            int v = __shfl_up_sync(0xffffffffu, incl, off);
            if ((tid & 31) >= off) incl += v;
        }
        if (tid < 256 && (tid & 31) == 31) swtot[tid >> 5] = incl;
        __syncthreads();
        if (tid == 0) {
            int s = 0;
#pragma unroll
            for (int w = 0; w < 8; ++w) { int t = swtot[w]; swoff[w] = s; s += t; }
        }
        __syncthreads();
        if (tid < 256) {
            int cum = incl + swoff[tid >> 5];
            int prev = cum - c;
            if (k >= prev && k < cum) {
                s_prefix = prefix | ((unsigned)tid << shift);
                s_k = k - prev;
            }
        }
        __syncthreads();
        prefix = s_prefix;
        k = s_k;
        __syncthreads();  // protect s_prefix/s_k and hist before next-round reuse
    }
    return __uint_as_float(prefix);
}

__global__ __launch_bounds__(1024) void thresh_gates_kernel(
    const float* __restrict__ qp,
    const float* __restrict__ cw1, const float* __restrict__ cw2,
    const float* __restrict__ cw3, const float* __restrict__ rw,
    const float* __restrict__ sweights) {
    int bid = blockIdx.x, tid = threadIdx.x;

    if (bid == 3) {   // scalar mixing weight G
        float s1 = block_reduce_sum_f(cw1[tid]);
        float s2 = block_reduce_sum_f(cw2[tid]);
        float s3 = block_reduce_sum_f(cw3[tid]);
        if (tid == 0) {
            float m1 = s1 * (1.f / 1024.f), m2 = s2 * (1.f / 1024.f), m3 = s3 * (1.f / 1024.f);
            d_Gmix = (m1 + 0.5f * m2 + 0.2f * m3) * sigm(rw[0]);
        }
        return;
    }

    const float* e = (bid == 0) ? d_e0 : (bid == 1) ? d_e1 : d_e2;
    float*       g = (bid == 0) ? d_g0 : (bid == 1) ? d_g1 : d_g2;
    int n = (bid == 0) ? B_ * 2048 : (bid == 1) ? B_ * 1024 : B_ * 512;
    int m = n >> 10;  // elements per thread (16/8/4)

    unsigned eb[16];
#pragma unroll
    for (int i = 0; i < 16; i++)
        eb[i] = (i < m) ? __float_as_uint(e[tid + (i << 10)]) : 0xffffffffu;

    // torch.quantile 'linear': idx = q*(n-1); interp between s[lo], s[lo+1]
    float qv = qp[0];
    float idxf = qv * (float)(n - 1);
    int lo = (int)floorf(idxf);
    if (lo < 0) lo = 0;
    if (lo > n - 1) lo = n - 1;
    int hi = lo + 1;
    if (hi > n - 1) hi = n - 1;
    float frac = idxf - (float)lo;

    float vlo = radix_select_kth(eb, m, lo);
    float vhi = (hi == lo) ? vlo : radix_select_kth(eb, m, hi);
    float thr = vlo * (1.0f - frac) + vhi * frac;

    // fused gate write for this scale
    float gval = sigm(sweights[bid]);
#pragma unroll
    for (int j = 0; j < 16; ++j) {
        if (j < m) {
            float ev = __uint_as_float(eb[j]);
            g[tid + (j << 10)] = (ev > thr) ? gval : 0.0f;
        }
    }
}

// --------------------------------------------------------------------------
// Pass 3: fused decompose + threshold + multi-level linear-upsample synthesis.
// Streaming recurrence per channel with 1-coarse-block lookahead.
//   up[2m]   = 0.25 R[m-1] + 0.75 R[m]      (index-clamp == reference clip)
//   up[2m+1] = 0.75 R[m]   + 0.25 R[m+1]
// Block mapping REVERSED so earliest CTAs consume the L2-hot tail of x that
// energy_kernel just streamed; out written with evict-first streaming stores.
// --------------------------------------------------------------------------
__device__ __forceinline__ void decomp_block(const float* __restrict__ p,
                                             float (&D0)[8], float (&D1)[4],
                                             float (&D2)[2], float& A3) {
    float v[16];
#pragma unroll
    for (int k = 0; k < 16; k++) v[k] = p[(size_t)k * C_];
    float a1[8];
#pragma unroll
    for (int j = 0; j < 8; j++) {
        D0[j] = (v[2 * j] - v[2 * j + 1]) * 0.5f;
        a1[j] = (v[2 * j] + v[2 * j + 1]) * 0.5f;
    }
    float a2[4];
#pragma unroll
    for (int j = 0; j < 4; j++) {
        D1[j] = (a1[2 * j] - a1[2 * j + 1]) * 0.5f;
        a2[j] = (a1[2 * j] + a1[2 * j + 1]) * 0.5f;
    }
    float a3[2];
#pragma unroll
    for (int j = 0; j < 2; j++) {
        D2[j] = (a2[2 * j] - a2[2 * j + 1]) * 0.5f;
        a3[j] = (a2[2 * j] + a2[2 * j + 1]) * 0.5f;
    }
    A3 = (a3[0] + a3[1]) * 0.5f;
}

__global__ __launch_bounds__(256) void recon_kernel(const float* __restrict__ x,
                                                    float* __restrict__ out,
                                                    const float* __restrict__ sweights) {
    int c  = blockIdx.x * 256 + threadIdx.x;
    int t0 = ((int)gridDim.y - 1 - (int)blockIdx.y) * CHUNK;  // reversed
    int b  = (B_ - 1) - (int)blockIdx.z;                       // reversed

    float sw3 = sigm(sweights[3]);
    float G   = d_Gmix;
    const float* xb = x   + (size_t)b * N_ * C_ + c;
    float*       ob = out + (size_t)b * N_ * C_ + c;
    const float* g0 = d_g0 + b * 2048;
    const float* g1 = d_g1 + b * 1024;
    const float* g2 = d_g2 + b * 512;

    float D0c[8], D1c[4], D2c[2], A3c;
    decomp_block(xb + (size_t)t0 * 16 * C_, D0c, D1c, D2c, A3c);

    float pR256, pR512, pR1024, pR2048;
    if (t0 == 0) {
        // left-edge clamp: prev values equal the first values
        float R = sw3 * A3c;
        pR256  = R;
        pR512  = R + g2[0] * D2c[0];
        pR1024 = pR512 + g1[0] * D1c[0];
        pR2048 = pR1024 + g0[0] * D0c[0];
    } else {
        // warm-up from halo block t0-1
        float D0p[8], D1p[4], D2p[2], A3p;
        decomp_block(xb + (size_t)(t0 - 1) * 16 * C_, D0p, D1p, D2p, A3p);
        float Rm = sw3 * A3p, Rc = sw3 * A3c;
        float R512m  = 0.75f * Rm + 0.25f * Rc + g2[2 * t0 - 1] * D2p[1];
        float R512_0 = 0.25f * Rm + 0.75f * Rc + g2[2 * t0]     * D2c[0];
        float R1024m  = 0.75f * R512m + 0.25f * R512_0 + g1[4 * t0 - 1] * D1p[3];
        float R1024_0 = 0.25f * R512m + 0.75f * R512_0 + g1[4 * t0]     * D1c[0];
        pR2048 = 0.75f * R1024m + 0.25f * R1024_0 + g0[8 * t0 - 1] * D0p[7];
        pR256 = Rm; pR512 = R512m; pR1024 = R1024m;
    }

#pragma unroll 1
    for (int tt = 0; tt < CHUNK; ++tt) {
        int t = t0 + tt;
        bool lastb = (t == NB - 1);
        int tn = lastb ? t : t + 1;

        float D0n[8], D1n[4], D2n[2], A3n;
        decomp_block(xb + (size_t)tn * 16 * C_, D0n, D1n, D2n, A3n);

        float cR256 = sw3 * A3c;
        float nR256 = lastb ? cR256 : sw3 * A3n;

        float r512_0 = 0.25f * pR256 + 0.75f * cR256 + g2[2 * t]     * D2c[0];
        float r512_1 = 0.75f * cR256 + 0.25f * nR256 + g2[2 * t + 1] * D2c[1];
        int i2 = 2 * t + 2; if (i2 > 511) i2 = 511;
        float nR512 = lastb ? r512_1
                            : (0.25f * cR256 + 0.75f * nR256 + g2[i2] * D2n[0]);

        float r1024_0 = 0.25f * pR512  + 0.75f * r512_0 + g1[4 * t]     * D1c[0];
        float r1024_1 = 0.75f * r512_0 + 0.25f * r512_1 + g1[4 * t + 1] * D1c[1];
        float r1024_2 = 0.25f * r512_0 + 0.75f * r512_1 + g1[4 * t + 2] * D1c[2];
        float r1024_3 = 0.75f * r512_1 + 0.25f * nR512  + g1[4 * t + 3] * D1c[3];
        int i1 = 4 * t + 4; if (i1 > 1023) i1 = 1023;
        float nR1024 = lastb ? r1024_3
                             : (0.25f * r512_1 + 0.75f * nR512 + g1[i1] * D1n[0]);

        float r2048[8];
        r2048[0] = 0.25f * pR1024  + 0.75f * r1024_0 + g0[8 * t + 0] * D0c[0];
        r2048[1] = 0.75f * r1024_0 + 0.25f * r1024_1 + g0[8 * t + 1] * D0c[1];
        r2048[2] = 0.25f * r1024_0 + 0.75f * r1024_1 + g0[8 * t + 2] * D0c[2];
        r2048[3] = 0.75f * r1024_1 + 0.25f * r1024_2 + g0[8 * t + 3] * D0c[3];
        r2048[4] = 0.25f * r1024_1 + 0.75f * r1024_2 + g0[8 * t + 4] * D0c[4];
        r2048[5] = 0.75f * r1024_2 + 0.25f * r1024_3 + g0[8 * t + 5] * D0c[5];
        r2048[6] = 0.25f * r1024_2 + 0.75f * r1024_3 + g0[8 * t + 6] * D0c[6];
        r2048[7] = 0.75f * r1024_3 + 0.25f * nR1024  + g0[8 * t + 7] * D0c[7];
        int i0 = 8 * t + 8; if (i0 > 2047) i0 = 2047;
        float nR2048 = lastb ? r2048[7]
                             : (0.25f * r1024_3 + 0.75f * nR1024 + g0[i0] * D0n[0]);

        float* op = ob + (size_t)t * 16 * C_;
        __stcs(op + 0 * C_,  (0.25f * pR2048   + 0.75f * r2048[0]) * G);
        __stcs(op + 1 * C_,  (0.75f * r2048[0] + 0.25f * r2048[1]) * G);
        __stcs(op + 2 * C_,  (0.25f * r2048[0] + 0.75f * r2048[1]) * G);
        __stcs(op + 3 * C_,  (0.75f * r2048[1] + 0.25f * r2048[2]) * G);
        __stcs(op + 4 * C_,  (0.25f * r2048[1] + 0.75f * r2048[2]) * G);
        __stcs(op + 5 * C_,  (0.75f * r2048[2] + 0.25f * r2048[3]) * G);
        __stcs(op + 6 * C_,  (0.25f * r2048[2] + 0.75f * r2048[3]) * G);
        __stcs(op + 7 * C_,  (0.75f * r2048[3] + 0.25f * r2048[4]) * G);
        __stcs(op + 8 * C_,  (0.25f * r2048[3] + 0.75f * r2048[4]) * G);
        __stcs(op + 9 * C_,  (0.75f * r2048[4] + 0.25f * r2048[5]) * G);
        __stcs(op + 10 * C_, (0.25f * r2048[4] + 0.75f * r2048[5]) * G);
        __stcs(op + 11 * C_, (0.75f * r2048[5] + 0.25f * r2048[6]) * G);
        __stcs(op + 12 * C_, (0.25f * r2048[5] + 0.75f * r2048[6]) * G);
        __stcs(op + 13 * C_, (0.75f * r2048[6] + 0.25f * r2048[7]) * G);
        __stcs(op + 14 * C_, (0.25f * r2048[6] + 0.75f * r2048[7]) * G);
        __stcs(op + 15 * C_, (0.75f * r2048[7] + 0.25f * nR2048)   * G);

        pR256 = cR256; pR512 = r512_1; pR1024 = r1024_3; pR2048 = r2048[7];
#pragma unroll
        for (int j = 0; j < 8; j++) D0c[j] = D0n[j];
#pragma unroll
        for (int j = 0; j < 4; j++) D1c[j] = D1n[j];
        D2c[0] = D2n[0]; D2c[1] = D2n[1];
        A3c = A3n;
    }
}

// --------------------------------------------------------------------------
// Launch
// --------------------------------------------------------------------------
extern "C" void kernel_launch(void* const* d_in, const int* in_sizes, int n_in,
                              void* d_out, int out_size) {
    const float* x   = (const float*)d_in[0];
    const float* cw1 = (const float*)d_in[1];
    const float* cw2 = (const float*)d_in[2];
    const float* cw3 = (const float*)d_in[3];
    const float* qp  = (const float*)d_in[4];
    const float* sw  = (const float*)d_in[5];
    const float* rw  = (const float*)d_in[6];
    float* out = (float*)d_out;

    energy_kernel<<<dim3(NB, B_), 256>>>(x);
    thresh_gates_kernel<<<4, 1024>>>(qp, cw1, cw2, cw3, rw, sw);
    recon_kernel<<<dim3(C_ / 256, NB / CHUNK, B_), 256>>>(x, out, sw);
}